// round 2
// baseline (speedup 1.0000x reference)
#include <cuda_runtime.h>
#include <math.h>

#define NN   50000
#define NE   800000
#define FIN  256
#define HD   128
#define EDIM 60
#define NEG_SLOPE 0.2f

// ---------------- scratch (static device arrays; no allocation) ----------------
__device__ float d_h [NN*HD];       // h1, then h2
__device__ float d_g [NN*HD];       // relu(layer1 out)  (GEMM2 input)
__device__ float d_z [NN*HD];       // layer2 out
__device__ float d_as[NN], d_ad[NN];
__device__ float d_aE1[NE], d_aE2[NE];
__device__ float d_esum1[NN], d_esum2[NN];
__device__ int   d_deg[NN];
__device__ int   d_rowstart[NN+1];
__device__ int   d_cursor[NN];
__device__ int   d_csr[NE];
__device__ float d_wvec1[EDIM], d_wvec2[EDIM];

// ---------------- init ----------------
__global__ void k_init() {
    int i = blockIdx.x*blockDim.x + threadIdx.x;
    if (i < NN) { d_deg[i]=0; d_esum1[i]=0.f; d_esum2[i]=0.f; d_cursor[i]=0; }
}

// wvec = We @ a_edge  (collapse the E x 60 x 128 GEMM into a 60-vector)
__global__ void k_wvec(const float* __restrict__ We1, const float* __restrict__ ae1,
                       const float* __restrict__ We2, const float* __restrict__ ae2) {
    int j = threadIdx.x;
    if (j < EDIM) {
        float s1=0.f, s2=0.f;
        for (int c=0;c<HD;c++){ s1 += We1[j*HD+c]*ae1[c]; s2 += We2[j*HD+c]*ae2[c]; }
        d_wvec1[j]=s1; d_wvec2[j]=s2;
    }
}

// per-edge edge-feature dots (both layers, one pass) + deg + per-node edge sums
__global__ void k_edgedot(const float* __restrict__ ef, const int* __restrict__ dst) {
    __shared__ float w1[EDIM], w2[EDIM];
    int t = threadIdx.x;
    if (t < EDIM) { w1[t]=d_wvec1[t]; w2[t]=d_wvec2[t]; }
    __syncthreads();
    int warp = (blockIdx.x*blockDim.x + t) >> 5;
    int lane = t & 31;
    if (warp >= NE) return;
    const float* row = ef + (size_t)warp*EDIM;
    float x0 = row[lane];                                 // lane < 32 < 60
    float v1 = x0*w1[lane], v2 = x0*w2[lane];
    if (lane < EDIM-32) {
        float x1 = row[lane+32];
        v1 += x1*w1[lane+32]; v2 += x1*w2[lane+32];
    }
    #pragma unroll
    for (int o=16;o;o>>=1){ v1 += __shfl_down_sync(~0u,v1,o); v2 += __shfl_down_sync(~0u,v2,o); }
    if (lane==0){
        d_aE1[warp]=v1; d_aE2[warp]=v2;
        int dd = dst[warp];
        atomicAdd(&d_esum1[dd], v1);
        atomicAdd(&d_esum2[dd], v2);
        atomicAdd(&d_deg[dd], 1);
    }
}

// single-block exclusive scan of deg -> rowstart
__global__ void k_scan() {
    __shared__ int sm[1024];
    __shared__ int base;
    int t = threadIdx.x;
    if (t==0){ base=0; d_rowstart[0]=0; }
    __syncthreads();
    for (int start=0; start<NN; start+=1024) {
        int i = start + t;
        int v = (i<NN) ? d_deg[i] : 0;
        sm[t]=v; __syncthreads();
        for (int o=1;o<1024;o<<=1){
            int add = (t>=o) ? sm[t-o] : 0;
            __syncthreads();
            sm[t] += add;
            __syncthreads();
        }
        if (i<NN) d_rowstart[i+1] = base + sm[t];
        __syncthreads();
        if (t==1023) base += sm[1023];
        __syncthreads();
    }
}

__global__ void k_scatter(const int* __restrict__ dst) {
    int e = blockIdx.x*blockDim.x + threadIdx.x;
    if (e < NE) {
        int d = dst[e];
        int pos = d_rowstart[d] + atomicAdd(&d_cursor[d], 1);
        d_csr[pos] = e;
    }
}

// ---------------- SGEMM: C[M,128] = A[M,K] @ B[K,128], fp32, 128x128x8 tiles ----
__global__ void __launch_bounds__(256) k_sgemm(const float* __restrict__ A,
                                               const float* __restrict__ B,
                                               float* __restrict__ C, int M, int K) {
    constexpr int BM=128, BN=128, BK=8, TM=8, TN=8;
    __shared__ float As[BK][BM];
    __shared__ float Bs[BK][BN];
    int tid  = threadIdx.x;
    int tcol = tid & 15;     // 0..15
    int trow = tid >> 4;     // 0..15
    int row0 = blockIdx.x * BM;
    int aRow = tid >> 1;             // 0..127
    int aCol = (tid & 1) * 4;        // 0 or 4
    int bRow = tid >> 5;             // 0..7
    int bCol = (tid & 31) * 4;       // 0..124
    float acc[TM][TN];
    #pragma unroll
    for (int i=0;i<TM;i++)
        #pragma unroll
        for (int j=0;j<TN;j++) acc[i][j]=0.f;

    for (int k0=0; k0<K; k0+=BK) {
        int ar = row0 + aRow;
        float4 a4 = make_float4(0.f,0.f,0.f,0.f);
        if (ar < M) a4 = *(const float4*)&A[(size_t)ar*K + k0 + aCol];
        As[aCol+0][aRow]=a4.x; As[aCol+1][aRow]=a4.y;
        As[aCol+2][aRow]=a4.z; As[aCol+3][aRow]=a4.w;
        *(float4*)&Bs[bRow][bCol] = *(const float4*)&B[(size_t)(k0+bRow)*BN + bCol];
        __syncthreads();
        #pragma unroll
        for (int k=0;k<BK;k++){
            float4 a0 = *(const float4*)&As[k][trow*TM];
            float4 a1 = *(const float4*)&As[k][trow*TM+4];
            float4 b0 = *(const float4*)&Bs[k][tcol*TN];
            float4 b1 = *(const float4*)&Bs[k][tcol*TN+4];
            float ar_[TM] = {a0.x,a0.y,a0.z,a0.w,a1.x,a1.y,a1.z,a1.w};
            float br_[TN] = {b0.x,b0.y,b0.z,b0.w,b1.x,b1.y,b1.z,b1.w};
            #pragma unroll
            for (int i=0;i<TM;i++)
                #pragma unroll
                for (int j=0;j<TN;j++) acc[i][j] += ar_[i]*br_[j];
        }
        __syncthreads();
    }
    #pragma unroll
    for (int i=0;i<TM;i++){
        int r = row0 + trow*TM + i;
        if (r < M) {
            float4 o0 = make_float4(acc[i][0],acc[i][1],acc[i][2],acc[i][3]);
            float4 o1 = make_float4(acc[i][4],acc[i][5],acc[i][6],acc[i][7]);
            *(float4*)&C[(size_t)r*BN + tcol*TN]     = o0;
            *(float4*)&C[(size_t)r*BN + tcol*TN + 4] = o1;
        }
    }
}

// per-node attention scalars: as[i] = h[i].a_src, ad[i] = h[i].a_dst
__global__ void k_alpha(const float* __restrict__ h,
                        const float* __restrict__ asrc, const float* __restrict__ adst) {
    int warp = (blockIdx.x*blockDim.x + threadIdx.x) >> 5;
    int lane = threadIdx.x & 31;
    if (warp >= NN) return;
    const float* row = h + (size_t)warp*HD;
    float s=0.f, d=0.f;
    #pragma unroll
    for (int q=0;q<4;q++){
        float v = row[lane+32*q];
        s += v*asrc[lane+32*q];
        d += v*adst[lane+32*q];
    }
    #pragma unroll
    for (int o=16;o;o>>=1){ s += __shfl_down_sync(~0u,s,o); d += __shfl_down_sync(~0u,d,o); }
    if (lane==0){ d_as[warp]=s; d_ad[warp]=d; }
}

__device__ __forceinline__ float lrelu(float x){ return x > 0.f ? x : NEG_SLOPE*x; }

// segment softmax + weighted aggregation, one 128-thread block per node.
// out[i] = (sum_j e^{a_j - m} h[s_j] + e^{a_self - m} h[i]) / (sum e^{.}) + b
__global__ void __launch_bounds__(128) k_aggregate(
        const float* __restrict__ h, const float* __restrict__ aE,
        const float* __restrict__ esum, const int* __restrict__ srcArr,
        const float* __restrict__ bias, float* __restrict__ out, int doRelu) {
    int i = blockIdx.x;
    int t = threadIdx.x;
    __shared__ float sm_e[128];
    __shared__ int   sm_s[128];
    __shared__ float red[128];
    int r0 = d_rowstart[i], r1 = d_rowstart[i+1];
    int degi = r1 - r0;
    float adi = d_ad[i];
    float aself = lrelu(d_as[i] + adi + esum[i]/fmaxf((float)degi, 1.f));
    // phase 1: max
    float m = aself;
    for (int j=t; j<degi; j+=128) {
        int e = d_csr[r0+j];
        m = fmaxf(m, lrelu(d_as[srcArr[e]] + adi + aE[e]));
    }
    red[t]=m; __syncthreads();
    #pragma unroll
    for (int o=64;o;o>>=1){ if (t<o) red[t]=fmaxf(red[t],red[t+o]); __syncthreads(); }
    m = red[0];
    __syncthreads();
    // phase 2: unnormalized accumulation, divide at end
    float acc = 0.f, dsum = 0.f;
    for (int j0=0; j0<degi; j0+=128) {
        int j = j0 + t;
        float ea = 0.f; int s = 0;
        if (j < degi) {
            int e = d_csr[r0+j];
            s = srcArr[e];
            ea = __expf(lrelu(d_as[s] + adi + aE[e]) - m);
        }
        sm_e[t]=ea; sm_s[t]=s;
        __syncthreads();
        int cnt = min(128, degi - j0);
        for (int q=0;q<cnt;q++){
            float c = sm_e[q];
            acc  += c * h[(size_t)sm_s[q]*HD + t];
            dsum += c;
        }
        __syncthreads();
    }
    float eself = __expf(aself - m);
    dsum += eself;
    acc  += eself * h[(size_t)i*HD + t];
    float o = acc/dsum + bias[t];
    if (doRelu) o = fmaxf(o, 0.f);
    out[(size_t)i*HD + t] = o;
}

// decode: out[j] = z[s_j].z[d_j] + z[s_{j+E/2}].z[d_{j+E/2}], warp per j
__global__ void k_decode(const int* __restrict__ srcArr, const int* __restrict__ dstArr,
                         float* __restrict__ out) {
    int warp = (blockIdx.x*blockDim.x + threadIdx.x) >> 5;
    int lane = threadIdx.x & 31;
    if (warp >= NE/2) return;
    const float* a1 = d_z + (size_t)srcArr[warp]*HD;
    const float* b1 = d_z + (size_t)dstArr[warp]*HD;
    const float* a2 = d_z + (size_t)srcArr[warp+NE/2]*HD;
    const float* b2 = d_z + (size_t)dstArr[warp+NE/2]*HD;
    float s = 0.f;
    #pragma unroll
    for (int q=0;q<4;q++){
        int c = lane + 32*q;
        s += a1[c]*b1[c] + a2[c]*b2[c];
    }
    #pragma unroll
    for (int o=16;o;o>>=1) s += __shfl_down_sync(~0u,s,o);
    if (lane==0) out[warp] = s;
}

// ---------------- launch ----------------
extern "C" void kernel_launch(void* const* d_in, const int* in_sizes, int n_in,
                              void* d_out, int out_size) {
    const float* x    = (const float*)d_in[0];
    const int*   ei   = (const int*)  d_in[1];
    const float* ef   = (const float*)d_in[2];
    // d_in[3] = batch_size (shape is static)
    const float* W1   = (const float*)d_in[4];
    const float* as1  = (const float*)d_in[5];
    const float* ad1  = (const float*)d_in[6];
    const float* We1  = (const float*)d_in[7];
    const float* ae1  = (const float*)d_in[8];
    const float* b1   = (const float*)d_in[9];
    const float* W2   = (const float*)d_in[10];
    const float* as2  = (const float*)d_in[11];
    const float* ad2  = (const float*)d_in[12];
    const float* We2  = (const float*)d_in[13];
    const float* ae2  = (const float*)d_in[14];
    const float* b2   = (const float*)d_in[15];
    const int* src = ei;
    const int* dst = ei + NE;

    float* h;  cudaGetSymbolAddress((void**)&h,  d_h);
    float* g;  cudaGetSymbolAddress((void**)&g,  d_g);
    float* z;  cudaGetSymbolAddress((void**)&z,  d_z);
    float* aE1; cudaGetSymbolAddress((void**)&aE1, d_aE1);
    float* aE2; cudaGetSymbolAddress((void**)&aE2, d_aE2);
    float* es1; cudaGetSymbolAddress((void**)&es1, d_esum1);
    float* es2; cudaGetSymbolAddress((void**)&es2, d_esum2);

    k_init<<<(NN+255)/256, 256>>>();
    k_wvec<<<1, 64>>>(We1, ae1, We2, ae2);
    k_edgedot<<<NE/8, 256>>>(ef, dst);          // 8 warps/block, warp per edge
    k_scan<<<1, 1024>>>();
    k_scatter<<<(NE+255)/256, 256>>>(dst);

    // layer 1
    k_sgemm<<<(NN+127)/128, 256>>>(x, W1, h, NN, FIN);
    k_alpha<<<(NN*32)/256, 256>>>(h, as1, ad1);
    k_aggregate<<<NN, 128>>>(h, aE1, es1, src, b1, g, 1);

    // layer 2
    k_sgemm<<<(NN+127)/128, 256>>>(g, W2, h, NN, HD);
    k_alpha<<<(NN*32)/256, 256>>>(h, as2, ad2);
    k_aggregate<<<NN, 128>>>(h, aE2, es2, src, b2, z, 0);

    // decode
    k_decode<<<(NE/2*32)/256, 256>>>(src, dst, (float*)d_out);
}